// round 16
// baseline (speedup 1.0000x reference)
#include <cuda_runtime.h>
#include <stdint.h>

// JitterSeqPredicton — JAX threefry (partitionable/XOR, detection-validated
// in R8/R9) jitter; OUTPUT IS FLOAT32 (the root cause of rounds 1-14:
// __output__ dtype is float32 per metadata, not int32).
// One CTA per row, [16384, 2048] tokens.
// (Verbatim resubmit of R15 — that round died to a broker/container flake.)

namespace {

constexpr int SEQ = 2048;
constexpr int NT  = 256;

__device__ __forceinline__ uint32_t rotl_(uint32_t x, int d) {
    return (x << d) | (x >> (32 - d));
}

// Threefry-2x32, 20 rounds (JAX threefry2x32_p).
__device__ __forceinline__ void threefry(uint32_t k0, uint32_t k1,
                                         uint32_t x0, uint32_t x1,
                                         uint32_t& o0, uint32_t& o1) {
    uint32_t k2 = k0 ^ k1 ^ 0x1BD11BDAu;
    x0 += k0; x1 += k1;
#define TF_R(r) { x0 += x1; x1 = rotl_(x1, r); x1 ^= x0; }
    TF_R(13) TF_R(15) TF_R(26) TF_R(6)
    x0 += k1; x1 += k2 + 1u;
    TF_R(17) TF_R(29) TF_R(16) TF_R(24)
    x0 += k2; x1 += k0 + 2u;
    TF_R(13) TF_R(15) TF_R(26) TF_R(6)
    x0 += k0; x1 += k1 + 3u;
    TF_R(17) TF_R(29) TF_R(16) TF_R(24)
    x0 += k1; x1 += k2 + 4u;
    TF_R(13) TF_R(15) TF_R(26) TF_R(6)
    x0 += k2; x1 += k0 + 5u;
#undef TF_R
    o0 = x0; o1 = x1;
}

// partitionable random_bits: lane0 ^ lane1 of tf(key, (0, i))
__device__ __forceinline__ uint32_t rb32(uint32_t k0, uint32_t k1, uint32_t i) {
    uint32_t a, b; threefry(k0, k1, 0u, i, a, b); return a ^ b;
}
// split child j: both lanes of tf(key, (0, j))
__device__ __forceinline__ void splitc(uint32_t k0, uint32_t k1, uint32_t j,
                                       uint32_t& c0, uint32_t& c1) {
    threefry(k0, k1, 0u, j, c0, c1);
}
__device__ __forceinline__ float u01(uint32_t bits) {
    return __uint_as_float((bits >> 9) | 0x3F800000u) - 1.0f;
}
// randint offset: ((h%span)*((2^16%span)^2%span) + l%span) % span
__device__ __forceinline__ uint32_t ri_off(uint32_t h, uint32_t l, uint32_t span) {
    uint32_t m = 65536u % span; m = (m * m) % span;
    return ((h % span) * m + (l % span)) % span;
}

__global__ __launch_bounds__(NT) void jitter_kernel(const int* __restrict__ xs,
                                                    float* __restrict__ out) {
    __shared__ int sx[SEQ];
    __shared__ uint32_t mant[SEQ];
    __shared__ int cum[SEQ];
    __shared__ int so[SEQ];
    __shared__ uint32_t hdr[24];
    __shared__ int sfirst;

    const int row = blockIdx.x;
    const int tid = threadIdx.x;
    const int* xr = xs + (size_t)row * SEQ;
    float* orow = out + (size_t)row * SEQ;

    if (tid == 0) sfirst = SEQ;
    __syncthreads();
    for (int i = tid; i < SEQ; i += NT) {
        int v = xr[i];
        sx[i] = v;
        if (v == 1) atomicMin(&sfirst, i);     // EOS_ID == 1
    }
    if (tid == 0) {
        uint32_t rk0, rk1;
        splitc(0u, 42u, (uint32_t)row, rk0, rk1);   // split(key(42), BS)[row]
        // k_u, k_p, k_rep_v, k_rep_p, k_ins_r, k_ins_n, k_ins_v, k_del_r, k_del_n
        for (uint32_t j = 0; j < 9; ++j) {
            uint32_t a, b;
            splitc(rk0, rk1, j, a, b);
            hdr[2 * j] = a; hdr[2 * j + 1] = b;
        }
        hdr[18] = rb32(hdr[0], hdr[1], 0u);     // u bits (scalar)
        hdr[19] = rb32(hdr[2], hdr[3], 0u);     // p bits
    }
    __syncthreads();

    const float u = u01(hdr[18]);
    if (u > 0.3f) {                             // JITTER_PROB: keep original
        for (int i = tid; i < SEQ; i += NT) orow[i] = (float)sx[i];
        return;
    }
    const int first = sfirst;
    const int eos = (first < SEQ) ? min(max(first, 1), SEQ - 4) : (SEQ / 2);
    const float p = u01(hdr[19]);

    // ---------------- branch 1: random replace ----------------
    if (p < 0.33f) {
        uint32_t kp0 = hdr[6], kp1 = hdr[7];
        uint32_t h0, h1, l0, l1;                // randint split(k_rep_v, 2)
        splitc(hdr[4], hdr[5], 0u, h0, h1);
        splitc(hdr[4], hdr[5], 1u, l0, l1);
        for (int i = tid; i < SEQ; i += NT) {
            int v = sx[i];
            if (i < eos) {
                float kp = u01(rb32(kp0, kp1, (uint32_t)i));
                if (!(kp > 0.2f))               // INSERT_PROB threshold
                    v = 2 + (int)ri_off(rb32(h0, h1, (uint32_t)i),
                                        rb32(l0, l1, (uint32_t)i), 31998u);
            }
            orow[i] = (float)v;
        }
        return;
    }

    // ---------------- branches 2/3: insert / delete ----------------
    const bool is_ins = (p < 0.66f);
    if (tid == 0) {
        uint32_t kn0 = is_ins ? hdr[10] : hdr[16];
        uint32_t kn1 = is_ins ? hdr[11] : hdr[17];
        uint32_t a0, a1, b0, b1;
        splitc(kn0, kn1, 0u, a0, a1);
        splitc(kn0, kn1, 1u, b0, b1);
        int maxn = (int)((float)(eos + 1) * 0.2f) + 2;
        hdr[20] = 1u + ri_off(rb32(a0, a1, 0u), rb32(b0, b1, 0u),
                              (uint32_t)(maxn - 1));
    }
    __syncthreads();
    const int nsel = (int)hdr[20];

    if (is_ins && (eos + 1 + nsel > SEQ)) {     // insert revert
        for (int i = tid; i < SEQ; i += NT) orow[i] = (float)sx[i];
        return;
    }

    // selection mantissas (positions >= eos get sentinel = never selected)
    {
        uint32_t kr0 = is_ins ? hdr[8] : hdr[14];
        uint32_t kr1 = is_ins ? hdr[9] : hdr[15];
        for (int i = tid; i < SEQ; i += NT)
            mant[i] = (i < eos) ? (rb32(kr0, kr1, (uint32_t)i) >> 9) : 0xFFFFFFFFu;
    }
    __syncthreads();

    // stable rank counting: sel(i) = rank(i) < nsel among i < eos
    for (int i = tid; i < SEQ; i += NT) {
        int flag = 0;
        if (i < eos) {
            uint32_t mi = mant[i];
            int r = 0;
            for (int j = 0; j < eos; ++j) {
                uint32_t mj = mant[j];
                r += (mj < mi) || (mj == mi && j < i);
            }
            flag = (r < nsel) ? 1 : 0;
        }
        cum[i] = flag;
    }
    __syncthreads();
    if (tid == 0) {                             // serial inclusive cumsum
        int run = 0;
        for (int i = 0; i < SEQ; ++i) { run += cum[i]; cum[i] = run; }
    }
    __syncthreads();
    for (int i = tid; i < SEQ; i += NT) so[i] = 0;   // PAD_ID
    __syncthreads();

    if (is_ins) {
        uint32_t h0, h1, l0, l1;                // randint split(k_ins_v, 2)
        splitc(hdr[12], hdr[13], 0u, h0, h1);
        splitc(hdr[12], hdr[13], 1u, l0, l1);
        for (int i = tid; i < SEQ; i += NT) {
            int c = cum[i];
            int sel = c - (i ? cum[i - 1] : 0);
            if (i <= eos) {
                int dest = i + c;               // orig_dest (mode='drop')
                if (dest < SEQ) so[dest] = sx[i];
            }
            if (sel) {
                int k = c - 1;                  // k-th inserted value
                so[i + c - 1] = 2 + (int)ri_off(rb32(h0, h1, (uint32_t)k),
                                                rb32(l0, l1, (uint32_t)k), 31998u);
            }
        }
    } else {
        for (int i = tid; i < SEQ; i += NT) {
            int c = cum[i];
            int sel = c - (i ? cum[i - 1] : 0);
            if (i <= eos && !sel) so[i - c] = sx[i];
        }
    }
    __syncthreads();
    for (int i = tid; i < SEQ; i += NT) orow[i] = (float)so[i];
}

}  // namespace

extern "C" void kernel_launch(void* const* d_in, const int* in_sizes, int n_in,
                              void* d_out, int out_size) {
    const int* xs = (const int*)d_in[0];
    float* out = (float*)d_out;                 // __output__ float32 !
    int rows = in_sizes[0] / SEQ;
    jitter_kernel<<<rows, NT>>>(xs, out);
}

// round 17
// speedup vs baseline: 2.3958x; 2.3958x over previous
#include <cuda_runtime.h>
#include <stdint.h>

// JitterSeqPredicton — validated threefry jitter (R16, rel_err=0), now
// optimized: bitonic sort replaces O(eos^2) rank counting, parallel scan
// replaces serial cumsum, parallel subkey derivation, vectorized copy
// fast-path for the ~70% un-jittered rows. Output float32.

namespace {

constexpr int SEQ = 2048;
constexpr int NT  = 256;

__device__ __forceinline__ uint32_t rotl_(uint32_t x, int d) {
    return (x << d) | (x >> (32 - d));
}

// Threefry-2x32, 20 rounds (JAX threefry2x32_p).
__device__ __forceinline__ void threefry(uint32_t k0, uint32_t k1,
                                         uint32_t x0, uint32_t x1,
                                         uint32_t& o0, uint32_t& o1) {
    uint32_t k2 = k0 ^ k1 ^ 0x1BD11BDAu;
    x0 += k0; x1 += k1;
#define TF_R(r) { x0 += x1; x1 = rotl_(x1, r); x1 ^= x0; }
    TF_R(13) TF_R(15) TF_R(26) TF_R(6)
    x0 += k1; x1 += k2 + 1u;
    TF_R(17) TF_R(29) TF_R(16) TF_R(24)
    x0 += k2; x1 += k0 + 2u;
    TF_R(13) TF_R(15) TF_R(26) TF_R(6)
    x0 += k0; x1 += k1 + 3u;
    TF_R(17) TF_R(29) TF_R(16) TF_R(24)
    x0 += k1; x1 += k2 + 4u;
    TF_R(13) TF_R(15) TF_R(26) TF_R(6)
    x0 += k2; x1 += k0 + 5u;
#undef TF_R
    o0 = x0; o1 = x1;
}

__device__ __forceinline__ uint32_t rb32(uint32_t k0, uint32_t k1, uint32_t i) {
    uint32_t a, b; threefry(k0, k1, 0u, i, a, b); return a ^ b;
}
__device__ __forceinline__ void splitc(uint32_t k0, uint32_t k1, uint32_t j,
                                       uint32_t& c0, uint32_t& c1) {
    threefry(k0, k1, 0u, j, c0, c1);
}
__device__ __forceinline__ float u01(uint32_t bits) {
    return __uint_as_float((bits >> 9) | 0x3F800000u) - 1.0f;
}
__device__ __forceinline__ uint32_t ri_off(uint32_t h, uint32_t l, uint32_t span) {
    uint32_t m = 65536u % span; m = (m * m) % span;
    return ((h % span) * m + (l % span)) % span;
}

__global__ __launch_bounds__(NT) void jitter_kernel(const int* __restrict__ xs,
                                                    float* __restrict__ out) {
    __shared__ int sx[SEQ];
    __shared__ unsigned long long sk[SEQ];
    __shared__ int sc[SEQ];
    __shared__ int so[SEQ];
    __shared__ uint32_t hdr[24];
    __shared__ int sfirst;
    __shared__ int ps[NT];

    const int row = blockIdx.x;
    const int tid = threadIdx.x;
    const int* xr = xs + (size_t)row * SEQ;
    float* orow = out + (size_t)row * SEQ;

    // ---- parallel key derivation: tid j in [0,9) computes subkey j ----
    if (tid < 9) {
        uint32_t rk0, rk1, a, b;
        splitc(0u, 42u, (uint32_t)row, rk0, rk1);   // split(key(42), BS)[row]
        splitc(rk0, rk1, (uint32_t)tid, a, b);
        hdr[2 * tid] = a; hdr[2 * tid + 1] = b;
        if (tid == 0) hdr[18] = rb32(a, b, 0u);     // u bits (k_u local)
        if (tid == 1) hdr[19] = rb32(a, b, 0u);     // p bits (k_p local)
        if (tid == 2) sfirst = SEQ;
    }
    __syncthreads();

    const float u = u01(hdr[18]);
    if (u > 0.3f) {                                 // ---- copy fast path ----
        const int4* x4 = (const int4*)xr;
        float4* o4 = (float4*)orow;
#pragma unroll
        for (int i = tid; i < SEQ / 4; i += NT) {
            int4 v = x4[i];
            o4[i] = make_float4((float)v.x, (float)v.y, (float)v.z, (float)v.w);
        }
        return;
    }

    // jittered row: load to smem + EOS scan
    for (int i = tid; i < SEQ; i += NT) {
        int v = xr[i];
        sx[i] = v;
        if (v == 1) atomicMin(&sfirst, i);          // EOS_ID == 1
    }
    __syncthreads();

    const int first = sfirst;
    const int eos = (first < SEQ) ? min(max(first, 1), SEQ - 4) : (SEQ / 2);
    const float p = u01(hdr[19]);

    // ---------------- branch 1: random replace ----------------
    if (p < 0.33f) {
        uint32_t kp0 = hdr[6], kp1 = hdr[7];
        uint32_t h0, h1, l0, l1;                    // randint split(k_rep_v, 2)
        splitc(hdr[4], hdr[5], 0u, h0, h1);
        splitc(hdr[4], hdr[5], 1u, l0, l1);
        for (int i = tid; i < SEQ; i += NT) {
            int v = sx[i];
            if (i < eos) {
                float kp = u01(rb32(kp0, kp1, (uint32_t)i));
                if (!(kp > 0.2f))                   // INSERT_PROB threshold
                    v = 2 + (int)ri_off(rb32(h0, h1, (uint32_t)i),
                                        rb32(l0, l1, (uint32_t)i), 31998u);
            }
            orow[i] = (float)v;
        }
        return;
    }

    // ---------------- branches 2/3: insert / delete ----------------
    const bool is_ins = (p < 0.66f);
    if (tid == 0) {
        uint32_t kn0 = is_ins ? hdr[10] : hdr[16];
        uint32_t kn1 = is_ins ? hdr[11] : hdr[17];
        uint32_t a0, a1, b0, b1;
        splitc(kn0, kn1, 0u, a0, a1);
        splitc(kn0, kn1, 1u, b0, b1);
        int maxn = (int)((float)(eos + 1) * 0.2f) + 2;
        hdr[20] = 1u + ri_off(rb32(a0, a1, 0u), rb32(b0, b1, 0u),
                              (uint32_t)(maxn - 1));
    }
    __syncthreads();
    const int nsel = (int)hdr[20];

    if (is_ins && (eos + 1 + nsel > SEQ)) {         // insert revert
        const int4* x4 = (const int4*)xr;
        float4* o4 = (float4*)orow;
        for (int i = tid; i < SEQ / 4; i += NT) {
            int4 v = x4[i];
            o4[i] = make_float4((float)v.x, (float)v.y, (float)v.z, (float)v.w);
        }
        return;
    }

    // packed (mantissa, index) keys; sentinel for i >= eos sorts last
    {
        uint32_t kr0 = is_ins ? hdr[8] : hdr[14];
        uint32_t kr1 = is_ins ? hdr[9] : hdr[15];
        for (int i = tid; i < SEQ; i += NT) {
            uint32_t vb = (i < eos) ? (rb32(kr0, kr1, (uint32_t)i) >> 9)
                                    : 0x800000u;
            sk[i] = (((unsigned long long)vb) << 16) | (unsigned)i;
        }
    }
    __syncthreads();

    // bitonic sort ascending: lexicographic (mant, index) == stable rank
    for (int k = 2; k <= SEQ; k <<= 1) {
        for (int j = k >> 1; j > 0; j >>= 1) {
#pragma unroll
            for (int i = tid; i < SEQ; i += NT) {
                int ixj = i ^ j;
                if (ixj > i) {
                    unsigned long long A = sk[i], B = sk[ixj];
                    bool up = ((i & k) == 0);
                    if ((A > B) == up) { sk[i] = B; sk[ixj] = A; }
                }
            }
            __syncthreads();
        }
    }

    // sel = first nsel sorted entries (real positions only)
    for (int i = tid; i < SEQ; i += NT) sc[i] = 0;
    __syncthreads();
    for (int t = tid; t < nsel; t += NT) {
        unsigned long long key = sk[t];
        if ((uint32_t)(key >> 16) < 0x800000u) sc[key & 0xFFFFu] = 1;
    }
    __syncthreads();

    // parallel inclusive scan of sc (8 elems/thread + Hillis-Steele)
    {
        const int base = tid * (SEQ / NT);
        int s = 0;
#pragma unroll
        for (int k = 0; k < SEQ / NT; ++k) s += sc[base + k];
        ps[tid] = s;
        __syncthreads();
        for (int off = 1; off < NT; off <<= 1) {
            int v = (tid >= off) ? ps[tid - off] : 0;
            __syncthreads();
            ps[tid] += v;
            __syncthreads();
        }
        int run = ps[tid] - s;
#pragma unroll
        for (int k = 0; k < SEQ / NT; ++k) {
            run += sc[base + k];
            sc[base + k] = run;
        }
    }
    __syncthreads();

    for (int i = tid; i < SEQ; i += NT) so[i] = 0;  // PAD_ID
    __syncthreads();

    if (is_ins) {
        uint32_t h0, h1, l0, l1;                    // randint split(k_ins_v, 2)
        splitc(hdr[12], hdr[13], 0u, h0, h1);
        splitc(hdr[12], hdr[13], 1u, l0, l1);
        for (int i = tid; i < SEQ; i += NT) {
            int c = sc[i];
            int sel = c - (i ? sc[i - 1] : 0);
            if (i <= eos) {
                int dest = i + c;                   // orig_dest (mode='drop')
                if (dest < SEQ) so[dest] = sx[i];
            }
            if (sel) {
                int k = c - 1;                      // k-th inserted value
                so[i + c - 1] = 2 + (int)ri_off(rb32(h0, h1, (uint32_t)k),
                                                rb32(l0, l1, (uint32_t)k), 31998u);
            }
        }
    } else {
        for (int i = tid; i < SEQ; i += NT) {
            int c = sc[i];
            int sel = c - (i ? sc[i - 1] : 0);
            if (i <= eos && !sel) so[i - c] = sx[i];
        }
    }
    __syncthreads();
    for (int i = tid; i < SEQ; i += NT) orow[i] = (float)so[i];
}

}  // namespace

extern "C" void kernel_launch(void* const* d_in, const int* in_sizes, int n_in,
                              void* d_out, int out_size) {
    const int* xs = (const int*)d_in[0];
    float* out = (float*)d_out;                     // __output__ float32
    int rows = in_sizes[0] / SEQ;
    jitter_kernel<<<rows, NT>>>(xs, out);
}